// round 16
// baseline (speedup 1.0000x reference)
#include <cuda_runtime.h>
#include <math.h>

#define MAXB 32
#define MAXP 24564
#define MAXO 32
#define LTILE 32             // rows per k_loss block
#define LTHREADS 128
#define ACHUNK 1024
#define NBIN 4096
#define SLICE 2048
#define CANDMAX 1024

// ---------------- scratch (zero-initialized at load; self-cleaning) -----------
__device__ float              d_lc [MAXB * MAXP];
__device__ int                d_m  [MAXB * MAXP];
__device__ unsigned long long d_bp [MAXB * MAXO];
__device__ unsigned int       d_hist[MAXB * NBIN];
__device__ float              d_cv [MAXB * CANDMAX];
__device__ int                d_ci [MAXB * CANDMAX];
__device__ int                d_nc [MAXB];
__device__ int                d_selbin[MAXB];
__device__ int                d_rem[MAXB];
__device__ double             g_loss_l;
__device__ double             g_loss_c;
__device__ int                g_num_pos[MAXB];
__device__ int                g_done;

// ---------------- helpers ------------------------------------------------------
__device__ __forceinline__ unsigned int su32(const void* p) {
    unsigned int a;
    asm("{ .reg .u64 t; cvta.to.shared.u64 t, %1; cvt.u32.u64 %0, t; }" : "=r"(a) : "l"(p));
    return a;
}
__device__ __forceinline__ void mbar_init(unsigned int mbar, unsigned int cnt) {
    asm volatile("mbarrier.init.shared.b64 [%0], %1;" :: "r"(mbar), "r"(cnt) : "memory");
}
__device__ __forceinline__ void mbar_expect_tx(unsigned int mbar, unsigned int bytes) {
    asm volatile("mbarrier.arrive.expect_tx.shared.b64 _, [%0], %1;" :: "r"(mbar), "r"(bytes) : "memory");
}
__device__ __forceinline__ void bulk_g2s(unsigned int dst, const void* src,
                                         unsigned int bytes, unsigned int mbar) {
    asm volatile(
        "cp.async.bulk.shared::cta.global.mbarrier::complete_tx::bytes [%0], [%1], %2, [%3];"
        :: "r"(dst), "l"(src), "r"(bytes), "r"(mbar) : "memory");
}
__device__ __forceinline__ void mbar_wait(unsigned int mbar, unsigned int parity) {
    asm volatile(
        "{\n\t"
        ".reg .pred P1;\n\t"
        "WL%=:\n\t"
        "mbarrier.try_wait.parity.acquire.cta.shared::cta.b64 P1, [%0], %1, 0x989680;\n\t"
        "@P1 bra.uni WD%=;\n\t"
        "bra.uni WL%=;\n\t"
        "WD%=:\n\t"
        "}"
        :: "r"(mbar), "r"(parity) : "memory");
}
__device__ __forceinline__ int lbin(float x) {
    int b = __float2int_rz(x * 256.0f);
    return min(b, NBIN - 1);
}

// ---------------- fused matching: shared staging, both argmax directions --------
__global__ __launch_bounds__(1024) void k_pair(
    const float* __restrict__ priors, const float* __restrict__ boxes,
    int B, int P, int O)
{
    __shared__ float4 sp[ACHUNK];     // priors corner form (16KB; reused for combine)
    __shared__ float  sa[ACHUNK];     // prior areas
    __shared__ float4 tb4[MAXO];
    __shared__ float  tarea[MAXO];

    int b  = blockIdx.y;
    int base = blockIdx.x * ACHUNK;
    int n  = min(ACHUNK, P - base);
    int t  = threadIdx.x;
    int w  = t >> 5, l = t & 31;

    // truth boxes to smem (+ lane-resident copy for phase B)
    if (t < O) {
        float4 bx = ((const float4*)boxes)[b * O + t];
        tb4[t] = bx;
        tarea[t] = (bx.z - bx.x) * (bx.w - bx.y);
    }

    // stage priors chunk (corner form + area); thread t holds prior base+t in regs
    float4 myp = make_float4(0.f, 0.f, 0.f, 0.f);
    float mya = 0.f;
    bool valid = (t < n);
    if (valid) {
        float4 pr = ((const float4*)priors)[base + t];
        float ax0 = pr.x - pr.z * 0.5f, ay0 = pr.y - pr.w * 0.5f;
        float ax1 = pr.x + pr.z * 0.5f, ay1 = pr.y + pr.w * 0.5f;
        myp = make_float4(ax0, ay0, ax1, ay1);
        mya = (ax1 - ax0) * (ay1 - ay0);
        sp[t] = myp;
        sa[t] = mya;
    }
    __syncthreads();

    // ---- phase A: per-prior argmax over truths (cross-mult, div-free) ----
    if (valid) {
        float ibest = 0.0f, dbest = 1.0f; int bidx = 0;
        #pragma unroll 8
        for (int o = 0; o < O; o++) {
            float4 tb = tb4[o];                 // broadcast LDS.128
            float areab = tarea[o];
            float lx = fmaxf(myp.x, tb.x), ly = fmaxf(myp.y, tb.y);
            float rx = fminf(myp.z, tb.z), ry = fminf(myp.w, tb.w);
            float ww = fmaxf(rx - lx, 0.0f), hh = fmaxf(ry - ly, 0.0f);
            float inter = ww * hh;
            float den = (mya + areab) - inter;  // > 0 always
            if (inter * dbest > ibest * den) { ibest = inter; dbest = den; bidx = o; }
        }
        bool pos = (2.0f * ibest >= dbest);     // iou >= 0.5
        d_m[(size_t)b * P + base + t] = bidx | (pos ? 32 : 0);
    }

    // ---- phase B: per-truth argmax over priors (lane = truth) ----
    int lo2 = (l < O) ? l : 0;
    float4 tb = tb4[lo2];
    float areab = tarea[lo2];

    int s = w * 32, e = min(s + 32, n);
    float ibest = 0.0f, dbest = 1.0f; int pbest = base + s;
    for (int i = s; i < e; i++) {
        float4 pr = sp[i];                      // broadcast LDS.128
        float area_a = sa[i];
        float lx = fmaxf(pr.x, tb.x), ly = fmaxf(pr.y, tb.y);
        float rx = fminf(pr.z, tb.z), ry = fminf(pr.w, tb.w);
        float ww = fmaxf(rx - lx, 0.0f), hh = fmaxf(ry - ly, 0.0f);
        float inter = ww * hh;
        float den = (area_a + areab) - inter;
        if (inter * dbest > ibest * den) { ibest = inter; dbest = den; pbest = base + i; }
    }
    __syncthreads();

    // combine across warps (reuse sp/sa as scratch)
    float* ci = (float*)sp;
    float* cd = ci + ACHUNK;
    int*   cp = (int*)(cd + ACHUNK);
    if (l < O) {
        ci[w * 32 + l] = ibest;
        cd[w * 32 + l] = dbest;
        cp[w * 32 + l] = pbest;
    }
    __syncthreads();
    if (t < (unsigned)O) {
        int o = t;
        float bi = ci[o], bd = cd[o]; int bp_ = cp[o];
        #pragma unroll 8
        for (int w2 = 1; w2 < 32; w2++) {
            float i2 = ci[w2 * 32 + o], d2 = cd[w2 * 32 + o];
            if (i2 * bd > bi * d2) { bi = i2; bd = d2; bp_ = cp[w2 * 32 + o]; }
        }
        float iou = bi / bd;                    // exact IEEE div: matches ref bits
        unsigned long long key =
            (((unsigned long long)__float_as_uint(iou)) << 32) |
            (unsigned long long)(0xFFFFFFFFu - (unsigned)bp_);
        atomicMax(&d_bp[b * O + o], key);
    }
}

// ---------------- loss: bulk-async staged tile + linear-bin hist ----------------
__device__ __forceinline__ float sl1(float x) {
    float d = fabsf(x);
    return (d < 1.0f) ? 0.5f * d * d : d - 0.5f;
}

__global__ __launch_bounds__(LTHREADS, 16) void k_loss(
    const float* __restrict__ loc, const float* __restrict__ conf,
    const float* __restrict__ priors, const float* __restrict__ boxes,
    const int* __restrict__ labels, int B, int P, int O, int C)
{
    extern __shared__ float sh[];                    // LTILE*C floats
    __shared__ __align__(8) unsigned long long mbar;
    __shared__ int srow[LTILE];
    __shared__ int slab[MAXO];

    int b  = blockIdx.y;
    int p0 = blockIdx.x * LTILE;
    int t  = threadIdx.x;
    int nrow = min(LTILE, P - p0);

    size_t srcOff = ((size_t)b * P + p0) * (size_t)C;
    const float* src = conf + srcOff;
    unsigned int bytes = (unsigned int)(nrow * C) * 4u;
    bool bulk_ok = ((bytes & 15u) == 0u) && (((srcOff * 4u) & 15u) == 0u);

    unsigned int mb = su32(&mbar);
    if (bulk_ok && t == 0) mbar_init(mb, 1);
    if (t < LTILE) srow[t] = -1;
    __syncthreads();
    if (bulk_ok) {
        if (t == 0) {
            mbar_expect_tx(mb, bytes);
            bulk_g2s(su32(sh), src, bytes, mb);
        }
    } else {
        for (int i = t; i < nrow * C; i += LTHREADS) sh[i] = src[i];
    }
    if (t < O) {   // overlapped with the bulk copy
        slab[t] = labels[b * O + t];
        unsigned long long key = d_bp[b * O + t];
        int pf = (int)(0xFFFFFFFFu - (unsigned)(key & 0xFFFFFFFFull));
        int rr = pf - p0;
        if (rr >= 0 && rr < nrow)
            atomicMax(&srow[rr], t);   // max o == last writer (ref loop order)
    }
    if (bulk_ok) mbar_wait(mb, 0);
    __syncthreads();

    // quad-per-row exp sums
    int r = t >> 2, q = t & 3;
    int h = (C + 3) >> 2;
    int c0 = q * h, c1 = min(c0 + h, C);
    float s0 = 0.f, s1 = 0.f, s2 = 0.f, s3 = 0.f;
    if (r < nrow) {
        const float* row = sh + r * C;
        int c = c0;
        for (; c + 3 < c1; c += 4) {
            s0 += __expf(row[c]);   s1 += __expf(row[c+1]);
            s2 += __expf(row[c+2]); s3 += __expf(row[c+3]);
        }
        for (; c < c1; c++) s0 += __expf(row[c]);
    }
    float s = (s0 + s1) + (s2 + s3);
    s += __shfl_xor_sync(0xffffffffu, s, 1);
    s += __shfl_xor_sync(0xffffffffu, s, 2);

    bool live = (q == 0) && (r < nrow);
    unsigned int lmask = __ballot_sync(0xffffffffu, live);

    if (live) {
        int p = p0 + r;
        float lse = __logf(s);

        size_t bp = (size_t)b * P + p;
        int idx; bool pos;
        int ov = srow[r];
        if (ov >= 0) { idx = ov; pos = true; }
        else { int m = d_m[bp]; idx = m & 31; pos = (m & 32) != 0; }

        int   cls = pos ? slab[idx] : 0;
        float ce  = lse - sh[r * C + cls];
        float lcv = pos ? 0.0f : ce;
        d_lc[bp] = lcv;
        if (pos) {
            atomicAdd(&g_loss_c, (double)ce);
            atomicAdd(&g_num_pos[b], 1);
            float4 tr = ((const float4*)boxes)[b * O + idx];
            float4 pv = ((const float4*)priors)[p];
            float gx = ((tr.x + tr.z) * 0.5f - pv.x) / (0.1f * pv.z);
            float gy = ((tr.y + tr.w) * 0.5f - pv.y) / (0.1f * pv.w);
            float gw = logf((tr.z - tr.x) / pv.z) / 0.2f;
            float gh = logf((tr.w - tr.y) / pv.w) / 0.2f;
            float4 lp = ((const float4*)loc)[bp];
            float l = sl1(lp.x - gx) + sl1(lp.y - gy) + sl1(lp.z - gw) + sl1(lp.w - gh);
            atomicAdd(&g_loss_l, (double)l);
        }
        unsigned int bin = (unsigned)lbin(lcv);
        unsigned int grp = __match_any_sync(lmask, bin);
        if ((t & 31) == (__ffs(grp) - 1))
            atomicAdd(&d_hist[b * NBIN + bin], __popc(grp));
    }
}

// ---------------- mine stage 0: per-batch selbin/rem from histogram -------------
__global__ __launch_bounds__(1024) void k_mine0(int B, int P) {
    int b = blockIdx.x;
    int t = threadIdx.x;
    int lane = t & 31, wid = t >> 5;

    __shared__ unsigned int wsum[32];

    int np = g_num_pos[b];
    long long K64 = 3LL * np;
    if (K64 > P - 1) K64 = P - 1;
    int K = (int)K64;
    if (K <= 0) {
        if (t == 0) { d_selbin[b] = NBIN; d_rem[b] = 0; }
        return;
    }

    uint4 hv = ((const uint4*)(d_hist + b * NBIN))[t];
    unsigned int tot = hv.x + hv.y + hv.z + hv.w;
    unsigned int pre = tot;
    #pragma unroll
    for (int off = 1; off < 32; off <<= 1) {
        unsigned int v = __shfl_up_sync(0xffffffffu, pre, off);
        if (lane >= off) pre += v;
    }
    if (lane == 31) wsum[wid] = pre;
    __syncthreads();
    if (wid == 0) {
        unsigned int v = wsum[lane];
        #pragma unroll
        for (int off = 1; off < 32; off <<= 1) {
            unsigned int u = __shfl_up_sync(0xffffffffu, v, off);
            if (lane >= off) v += u;
        }
        wsum[lane] = v;
    }
    __syncthreads();
    unsigned int total = wsum[31];
    unsigned int incl  = pre + (wid > 0 ? wsum[wid - 1] : 0u);
    unsigned int above = total - incl;
    {
        unsigned int hbin[4] = { hv.x, hv.y, hv.z, hv.w };
        unsigned int a = above;
        #pragma unroll
        for (int j = 3; j >= 0; j--) {
            unsigned int c = hbin[j];
            if (a < (unsigned)K && a + c >= (unsigned)K) {
                d_selbin[b] = 4 * t + j;
                d_rem[b] = K - (int)a;
            }
            a += c;
        }
    }
}

// ---------------- mine stage 1: parallel streaming sum + candidate collect ------
__global__ __launch_bounds__(1024) void k_mine1(int B, int P) {
    int b = blockIdx.y;
    int split = blockIdx.x;
    const float* lc = d_lc + (size_t)b * P;
    int t = threadIdx.x;
    int lane = t & 31, wid = t >> 5;

    __shared__ double sred[32];

    int selbin = d_selbin[b];

    double part = 0.0;
    #pragma unroll
    for (int j = 0; j < SLICE / 1024; j++) {
        int p = split * SLICE + j * 1024 + t;
        if (p < P) {
            float x = lc[p];
            int bin = lbin(x);
            if (bin > selbin) part += (double)x;
            else if (bin == selbin) {
                int k = atomicAdd(&d_nc[b], 1);
                if (k < CANDMAX) { d_cv[b * CANDMAX + k] = x; d_ci[b * CANDMAX + k] = p; }
            }
        }
    }
    #pragma unroll
    for (int off = 16; off; off >>= 1)
        part += __shfl_xor_sync(0xffffffffu, part, off);
    if (lane == 0) sred[wid] = part;
    __syncthreads();
    if (wid == 0) {
        double tt = sred[lane];
        #pragma unroll
        for (int off = 16; off; off >>= 1)
            tt += __shfl_xor_sync(0xffffffffu, tt, off);
        if (lane == 0 && tt != 0.0) atomicAdd(&g_loss_c, tt);
    }
}

// ---------------- mine stage 2: rank candidates + finalize + reset --------------
__global__ __launch_bounds__(256) void k_mine2(float* out, int B, int P, int O) {
    int b = blockIdx.x;
    int t = threadIdx.x;
    int lane = t & 31, wid = t >> 5;

    __shared__ double sred[8];

    int rem = d_rem[b];

    double part = 0.0;
    if (rem > 0) {
        int nc = min(d_nc[b], CANDMAX);
        for (int i = t; i < nc; i += 256) {
            float xi = d_cv[b * CANDMAX + i]; int ii = d_ci[b * CANDMAX + i];
            int rank = 0;
            for (int j = 0; j < nc; j++) {
                float xj = d_cv[b * CANDMAX + j];
                rank += (xj > xi) || (xj == xi && d_ci[b * CANDMAX + j] < ii);
            }
            if (rank < rem) part += (double)xi;
        }
    }

    #pragma unroll
    for (int off = 16; off; off >>= 1)
        part += __shfl_xor_sync(0xffffffffu, part, off);
    if (lane == 0) sred[wid] = part;
    __syncthreads();
    if (wid == 0 && lane < 8) {
        double tt = sred[lane];
        #pragma unroll
        for (int off = 1; off < 8; off <<= 1)
            tt += __shfl_xor_sync(0xffu, tt, off);
        if (lane == 0 && rem > 0) atomicAdd(&g_loss_c, tt);
    }

    // resets for next replay
    if (t < O) d_bp[b * O + t] = 0ull;
    if (t == 0) d_nc[b] = 0;
    {
        uint4 z = make_uint4(0u, 0u, 0u, 0u);
        uint4* hw = (uint4*)(d_hist + b * NBIN);
        #pragma unroll
        for (int j = 0; j < 4; j++) hw[t * 4 + j] = z;
    }

    __syncthreads();
    if (t == 0) {
        __threadfence();
        if (atomicAdd(&g_done, 1) == B - 1) {
            double N = 0.0;
            for (int i = 0; i < B; i++) N += (double)g_num_pos[i];
            float Nf = (float)N;
            out[0] = (float)g_loss_l / Nf + (float)g_loss_c / Nf;
            g_loss_l = 0.0; g_loss_c = 0.0; g_done = 0;
            for (int i = 0; i < B; i++) g_num_pos[i] = 0;
        }
    }
}

// ---------------- launch -----------------------------------------------------------
extern "C" void kernel_launch(void* const* d_in, const int* in_sizes, int n_in,
                              void* d_out, int out_size)
{
    const float* loc    = (const float*)d_in[0];
    const float* conf   = (const float*)d_in[1];
    const float* priors = (const float*)d_in[2];
    const float* boxes  = (const float*)d_in[3];
    const int*   labels = (const int*)  d_in[4];

    int P = in_sizes[2] / 4;
    int B = in_sizes[0] / (P * 4);
    int C = (int)((long long)in_sizes[1] / ((long long)B * P));
    int O = in_sizes[4] / B;

    dim3 gp((P + ACHUNK - 1) / ACHUNK, B);
    k_pair<<<gp, 1024>>>(priors, boxes, B, P, O);

    dim3 g2((P + LTILE - 1) / LTILE, B);
    size_t smem = (size_t)LTILE * C * sizeof(float);
    k_loss<<<g2, LTHREADS, smem>>>(loc, conf, priors, boxes, labels, B, P, O, C);

    k_mine0<<<B, 1024>>>(B, P);

    dim3 gm1((P + SLICE - 1) / SLICE, B);
    k_mine1<<<gm1, 1024>>>(B, P);

    k_mine2<<<B, 256>>>((float*)d_out, B, P, O);
}

// round 17
// speedup vs baseline: 1.0284x; 1.0284x over previous
#include <cuda_runtime.h>
#include <math.h>

#define MAXB 32
#define MAXP 24564
#define MAXO 32
#define LTILE 32             // rows per k_loss block
#define LTHREADS 128
#define ACHUNK 1024
#define NBIN 4096
#define CANDMAX 1024
#define M1SPLIT 3            // mine1 splits per batch (float4 units)
#define M1CHUNK 2048         // float4 per split (3*2048 >= 6141)

// ---------------- scratch (zero-initialized at load; self-cleaning) -----------
__device__ float              d_lc [MAXB * MAXP];
__device__ int                d_m  [MAXB * MAXP];
__device__ unsigned long long d_bp [MAXB * MAXO];
__device__ unsigned int       d_hist[MAXB * NBIN];
__device__ float              d_cv [MAXB * CANDMAX];
__device__ int                d_ci [MAXB * CANDMAX];
__device__ int                d_nc [MAXB];
__device__ int                d_selbin[MAXB];
__device__ int                d_rem[MAXB];
__device__ double             g_loss_l;
__device__ double             g_loss_c;
__device__ int                g_num_pos[MAXB];
__device__ int                g_done;

// ---------------- helpers ------------------------------------------------------
__device__ __forceinline__ unsigned int su32(const void* p) {
    unsigned int a;
    asm("{ .reg .u64 t; cvta.to.shared.u64 t, %1; cvt.u32.u64 %0, t; }" : "=r"(a) : "l"(p));
    return a;
}
__device__ __forceinline__ void mbar_init(unsigned int mbar, unsigned int cnt) {
    asm volatile("mbarrier.init.shared.b64 [%0], %1;" :: "r"(mbar), "r"(cnt) : "memory");
}
__device__ __forceinline__ void mbar_expect_tx(unsigned int mbar, unsigned int bytes) {
    asm volatile("mbarrier.arrive.expect_tx.shared.b64 _, [%0], %1;" :: "r"(mbar), "r"(bytes) : "memory");
}
__device__ __forceinline__ void bulk_g2s(unsigned int dst, const void* src,
                                         unsigned int bytes, unsigned int mbar) {
    asm volatile(
        "cp.async.bulk.shared::cta.global.mbarrier::complete_tx::bytes [%0], [%1], %2, [%3];"
        :: "r"(dst), "l"(src), "r"(bytes), "r"(mbar) : "memory");
}
__device__ __forceinline__ void mbar_wait(unsigned int mbar, unsigned int parity) {
    asm volatile(
        "{\n\t"
        ".reg .pred P1;\n\t"
        "WL%=:\n\t"
        "mbarrier.try_wait.parity.acquire.cta.shared::cta.b64 P1, [%0], %1, 0x989680;\n\t"
        "@P1 bra.uni WD%=;\n\t"
        "bra.uni WL%=;\n\t"
        "WD%=:\n\t"
        "}"
        :: "r"(mbar), "r"(parity) : "memory");
}
__device__ __forceinline__ int lbin(float x) {
    int b = __float2int_rz(x * 256.0f);
    return min(b, NBIN - 1);
}

// ---------------- per-prior argmax over truths: cross-mult, div-free ------------
__global__ __launch_bounds__(256) void k_match(
    const float* __restrict__ priors, const float* __restrict__ boxes,
    int B, int P, int O)
{
    int b = blockIdx.y;
    int p = blockIdx.x * blockDim.x + threadIdx.x;
    bool valid = (p < P);
    int  pc = valid ? p : (P - 1);

    __shared__ float4 tb4[MAXO];
    __shared__ float  sarea[MAXO];
    if (threadIdx.x < O) {
        float4 t = ((const float4*)boxes)[b * O + threadIdx.x];
        tb4[threadIdx.x] = t;
        sarea[threadIdx.x] = (t.z - t.x) * (t.w - t.y);
    }
    __syncthreads();

    float4 pr = ((const float4*)priors)[pc];
    float ax0 = pr.x - pr.z * 0.5f, ay0 = pr.y - pr.w * 0.5f;
    float ax1 = pr.x + pr.z * 0.5f, ay1 = pr.y + pr.w * 0.5f;
    float area_a = (ax1 - ax0) * (ay1 - ay0);

    float ibest = 0.0f, dbest = 1.0f; int bidx = 0;
    #pragma unroll 8
    for (int o = 0; o < O; o++) {
        float4 t = tb4[o];
        float areab = sarea[o];
        float lx = fmaxf(ax0, t.x), ly = fmaxf(ay0, t.y);
        float rx = fminf(ax1, t.z), ry = fminf(ay1, t.w);
        float w = fmaxf(rx - lx, 0.0f), h = fmaxf(ry - ly, 0.0f);
        float inter = w * h;
        float den = (area_a + areab) - inter;
        if (inter * dbest > ibest * den) { ibest = inter; dbest = den; bidx = o; }
    }
    if (valid) {
        bool pos = (2.0f * ibest >= dbest);
        d_m[(size_t)b * P + p] = bidx | (pos ? 32 : 0);
    }
}

// ---------------- per-truth argmax over priors: lane = truth --------------------
__global__ __launch_bounds__(1024) void k_argmax(
    const float* __restrict__ priors, const float* __restrict__ boxes,
    int B, int P, int O)
{
    __shared__ float4 sp[ACHUNK];
    __shared__ float  sa[ACHUNK];
    int b  = blockIdx.y;
    int base = blockIdx.x * ACHUNK;
    int n  = min(ACHUNK, P - base);
    int w  = threadIdx.x >> 5, l = threadIdx.x & 31;

    int lo = (l < O) ? l : 0;
    float4 t = ((const float4*)boxes)[b * O + lo];
    float areab = (t.z - t.x) * (t.w - t.y);

    for (int i = threadIdx.x; i < n; i += 1024) {
        float4 pr = ((const float4*)priors)[base + i];
        float ax0 = pr.x - pr.z * 0.5f, ay0 = pr.y - pr.w * 0.5f;
        float ax1 = pr.x + pr.z * 0.5f, ay1 = pr.y + pr.w * 0.5f;
        sp[i] = make_float4(ax0, ay0, ax1, ay1);
        sa[i] = (ax1 - ax0) * (ay1 - ay0);
    }
    __syncthreads();

    int s = w * 32, e = min(s + 32, n);
    float ibest = 0.0f, dbest = 1.0f; int pbest = base + s;
    for (int i = s; i < e; i++) {
        float4 pr = sp[i];
        float area_a = sa[i];
        float lx = fmaxf(pr.x, t.x), ly = fmaxf(pr.y, t.y);
        float rx = fminf(pr.z, t.z), ry = fminf(pr.w, t.w);
        float ww = fmaxf(rx - lx, 0.0f), hh = fmaxf(ry - ly, 0.0f);
        float inter = ww * hh;
        float den = (area_a + areab) - inter;
        if (inter * dbest > ibest * den) { ibest = inter; dbest = den; pbest = base + i; }
    }
    __syncthreads();

    float* ci = (float*)sp;
    float* cd = ci + ACHUNK;
    int*   cp = (int*)(cd + ACHUNK);
    if (l < O) {
        ci[w * 32 + l] = ibest;
        cd[w * 32 + l] = dbest;
        cp[w * 32 + l] = pbest;
    }
    __syncthreads();
    if (threadIdx.x < (unsigned)O) {
        int o = threadIdx.x;
        float bi = ci[o], bd = cd[o]; int bp_ = cp[o];
        #pragma unroll 8
        for (int w2 = 1; w2 < 32; w2++) {
            float i2 = ci[w2 * 32 + o], d2 = cd[w2 * 32 + o];
            if (i2 * bd > bi * d2) { bi = i2; bd = d2; bp_ = cp[w2 * 32 + o]; }
        }
        float iou = bi / bd;                     // exact IEEE div: matches ref bits
        unsigned long long key =
            (((unsigned long long)__float_as_uint(iou)) << 32) |
            (unsigned long long)(0xFFFFFFFFu - (unsigned)bp_);
        atomicMax(&d_bp[b * O + o], key);
    }
}

// ---------------- loss: bulk-async staged tile + linear-bin hist ----------------
__device__ __forceinline__ float sl1(float x) {
    float d = fabsf(x);
    return (d < 1.0f) ? 0.5f * d * d : d - 0.5f;
}

__global__ __launch_bounds__(LTHREADS, 16) void k_loss(
    const float* __restrict__ loc, const float* __restrict__ conf,
    const float* __restrict__ priors, const float* __restrict__ boxes,
    const int* __restrict__ labels, int B, int P, int O, int C)
{
    extern __shared__ float sh[];                    // LTILE*C floats
    __shared__ __align__(8) unsigned long long mbar;
    __shared__ int srow[LTILE];
    __shared__ int slab[MAXO];

    int b  = blockIdx.y;
    int p0 = blockIdx.x * LTILE;
    int t  = threadIdx.x;
    int nrow = min(LTILE, P - p0);

    size_t srcOff = ((size_t)b * P + p0) * (size_t)C;
    const float* src = conf + srcOff;
    unsigned int bytes = (unsigned int)(nrow * C) * 4u;
    bool bulk_ok = ((bytes & 15u) == 0u) && (((srcOff * 4u) & 15u) == 0u);

    unsigned int mb = su32(&mbar);
    if (bulk_ok && t == 0) mbar_init(mb, 1);
    if (t < LTILE) srow[t] = -1;
    __syncthreads();
    if (bulk_ok) {
        if (t == 0) {
            mbar_expect_tx(mb, bytes);
            bulk_g2s(su32(sh), src, bytes, mb);
        }
    } else {
        for (int i = t; i < nrow * C; i += LTHREADS) sh[i] = src[i];
    }

    // early independent load: per-prior match result (hides LDG latency)
    int r = t >> 2, q = t & 3;
    int m_pref = 0;
    bool live = (q == 0) && (r < nrow);
    if (live) m_pref = d_m[(size_t)b * P + p0 + r];

    if (t < O) {   // overlapped with the bulk copy
        slab[t] = labels[b * O + t];
        unsigned long long key = d_bp[b * O + t];
        int pf = (int)(0xFFFFFFFFu - (unsigned)(key & 0xFFFFFFFFull));
        int rr = pf - p0;
        if (rr >= 0 && rr < nrow)
            atomicMax(&srow[rr], t);   // max o == last writer (ref loop order)
    }
    if (bulk_ok) mbar_wait(mb, 0);
    __syncthreads();

    // quad-per-row exp sums
    int h = (C + 3) >> 2;
    int c0 = q * h, c1 = min(c0 + h, C);
    float s0 = 0.f, s1 = 0.f, s2 = 0.f, s3 = 0.f;
    if (r < nrow) {
        const float* row = sh + r * C;
        int c = c0;
        for (; c + 3 < c1; c += 4) {
            s0 += __expf(row[c]);   s1 += __expf(row[c+1]);
            s2 += __expf(row[c+2]); s3 += __expf(row[c+3]);
        }
        for (; c < c1; c++) s0 += __expf(row[c]);
    }
    float s = (s0 + s1) + (s2 + s3);
    s += __shfl_xor_sync(0xffffffffu, s, 1);
    s += __shfl_xor_sync(0xffffffffu, s, 2);

    unsigned int lmask = __ballot_sync(0xffffffffu, live);

    if (live) {
        int p = p0 + r;
        float lse = __logf(s);

        size_t bp = (size_t)b * P + p;
        int idx; bool pos;
        int ov = srow[r];
        if (ov >= 0) { idx = ov; pos = true; }
        else { idx = m_pref & 31; pos = (m_pref & 32) != 0; }

        int   cls = pos ? slab[idx] : 0;
        float ce  = lse - sh[r * C + cls];
        float lcv = pos ? 0.0f : ce;
        d_lc[bp] = lcv;
        if (pos) {
            atomicAdd(&g_loss_c, (double)ce);
            atomicAdd(&g_num_pos[b], 1);
            float4 tr = ((const float4*)boxes)[b * O + idx];
            float4 pv = ((const float4*)priors)[p];
            float gx = ((tr.x + tr.z) * 0.5f - pv.x) / (0.1f * pv.z);
            float gy = ((tr.y + tr.w) * 0.5f - pv.y) / (0.1f * pv.w);
            float gw = logf((tr.z - tr.x) / pv.z) / 0.2f;
            float gh = logf((tr.w - tr.y) / pv.w) / 0.2f;
            float4 lp = ((const float4*)loc)[bp];
            float l = sl1(lp.x - gx) + sl1(lp.y - gy) + sl1(lp.z - gw) + sl1(lp.w - gh);
            atomicAdd(&g_loss_l, (double)l);
        }
        unsigned int bin = (unsigned)lbin(lcv);
        unsigned int grp = __match_any_sync(lmask, bin);
        if ((t & 31) == (__ffs(grp) - 1))
            atomicAdd(&d_hist[b * NBIN + bin], __popc(grp));
    }
}

// ---------------- mine stage 0: per-batch selbin/rem from histogram -------------
__global__ __launch_bounds__(1024) void k_mine0(int B, int P) {
    int b = blockIdx.x;
    int t = threadIdx.x;
    int lane = t & 31, wid = t >> 5;

    __shared__ unsigned int wsum[32];

    int np = g_num_pos[b];
    long long K64 = 3LL * np;
    if (K64 > P - 1) K64 = P - 1;
    int K = (int)K64;
    if (K <= 0) {
        if (t == 0) { d_selbin[b] = NBIN; d_rem[b] = 0; }
        return;
    }

    uint4 hv = ((const uint4*)(d_hist + b * NBIN))[t];
    unsigned int tot = hv.x + hv.y + hv.z + hv.w;
    unsigned int pre = tot;
    #pragma unroll
    for (int off = 1; off < 32; off <<= 1) {
        unsigned int v = __shfl_up_sync(0xffffffffu, pre, off);
        if (lane >= off) pre += v;
    }
    if (lane == 31) wsum[wid] = pre;
    __syncthreads();
    if (wid == 0) {
        unsigned int v = wsum[lane];
        #pragma unroll
        for (int off = 1; off < 32; off <<= 1) {
            unsigned int u = __shfl_up_sync(0xffffffffu, v, off);
            if (lane >= off) v += u;
        }
        wsum[lane] = v;
    }
    __syncthreads();
    unsigned int total = wsum[31];
    unsigned int incl  = pre + (wid > 0 ? wsum[wid - 1] : 0u);
    unsigned int above = total - incl;
    {
        unsigned int hbin[4] = { hv.x, hv.y, hv.z, hv.w };
        unsigned int a = above;
        #pragma unroll
        for (int j = 3; j >= 0; j--) {
            unsigned int c = hbin[j];
            if (a < (unsigned)K && a + c >= (unsigned)K) {
                d_selbin[b] = 4 * t + j;
                d_rem[b] = K - (int)a;
            }
            a += c;
        }
    }
}

// ---------------- mine stage 1: float4 streaming sum + candidate collect --------
__global__ __launch_bounds__(1024) void k_mine1(int B, int P) {
    int b = blockIdx.y;
    int split = blockIdx.x;
    int t = threadIdx.x;
    int lane = t & 31, wid = t >> 5;

    __shared__ double sred[32];

    int selbin = d_selbin[b];
    int n4 = P >> 2;                       // P % 4 == 0 for this dataset; tail below
    const float4* lc4 = (const float4*)(d_lc + (size_t)b * P);

    double part = 0.0;
    #pragma unroll
    for (int j = 0; j < M1CHUNK / 1024; j++) {
        int i4 = split * M1CHUNK + j * 1024 + t;
        if (i4 < n4) {
            float4 v = lc4[i4];
            float xs[4] = { v.x, v.y, v.z, v.w };
            #pragma unroll
            for (int e = 0; e < 4; e++) {
                float x = xs[e];
                int bin = lbin(x);
                if (bin > selbin) part += (double)x;
                else if (bin == selbin) {
                    int k = atomicAdd(&d_nc[b], 1);
                    if (k < CANDMAX) {
                        d_cv[b * CANDMAX + k] = x;
                        d_ci[b * CANDMAX + k] = i4 * 4 + e;
                    }
                }
            }
        }
    }
    // scalar tail (P not multiple of 4): handled by split 0
    if (split == 0) {
        int p = n4 * 4 + t;
        if (p < P) {
            float x = d_lc[(size_t)b * P + p];
            int bin = lbin(x);
            if (bin > selbin) part += (double)x;
            else if (bin == selbin) {
                int k = atomicAdd(&d_nc[b], 1);
                if (k < CANDMAX) { d_cv[b * CANDMAX + k] = x; d_ci[b * CANDMAX + k] = p; }
            }
        }
    }

    #pragma unroll
    for (int off = 16; off; off >>= 1)
        part += __shfl_xor_sync(0xffffffffu, part, off);
    if (lane == 0) sred[wid] = part;
    __syncthreads();
    if (wid == 0) {
        double tt = sred[lane];
        #pragma unroll
        for (int off = 16; off; off >>= 1)
            tt += __shfl_xor_sync(0xffffffffu, tt, off);
        if (lane == 0 && tt != 0.0) atomicAdd(&g_loss_c, tt);
    }
}

// ---------------- mine stage 2: rank candidates + finalize + reset --------------
__global__ __launch_bounds__(256) void k_mine2(float* out, int B, int P, int O) {
    int b = blockIdx.x;
    int t = threadIdx.x;
    int lane = t & 31, wid = t >> 5;

    __shared__ double sred[8];

    int rem = d_rem[b];

    double part = 0.0;
    if (rem > 0) {
        int nc = min(d_nc[b], CANDMAX);
        for (int i = t; i < nc; i += 256) {
            float xi = d_cv[b * CANDMAX + i]; int ii = d_ci[b * CANDMAX + i];
            int rank = 0;
            for (int j = 0; j < nc; j++) {
                float xj = d_cv[b * CANDMAX + j];
                rank += (xj > xi) || (xj == xi && d_ci[b * CANDMAX + j] < ii);
            }
            if (rank < rem) part += (double)xi;
        }
    }

    #pragma unroll
    for (int off = 16; off; off >>= 1)
        part += __shfl_xor_sync(0xffffffffu, part, off);
    if (lane == 0) sred[wid] = part;
    __syncthreads();
    if (wid == 0 && lane < 8) {
        double tt = sred[lane];
        #pragma unroll
        for (int off = 1; off < 8; off <<= 1)
            tt += __shfl_xor_sync(0xffu, tt, off);
        if (lane == 0 && rem > 0) atomicAdd(&g_loss_c, tt);
    }

    // resets for next replay
    if (t < O) d_bp[b * O + t] = 0ull;
    if (t == 0) d_nc[b] = 0;
    {
        uint4 z = make_uint4(0u, 0u, 0u, 0u);
        uint4* hw = (uint4*)(d_hist + b * NBIN);
        #pragma unroll
        for (int j = 0; j < 4; j++) hw[t * 4 + j] = z;
    }

    __syncthreads();
    if (t == 0) {
        __threadfence();
        if (atomicAdd(&g_done, 1) == B - 1) {
            double N = 0.0;
            for (int i = 0; i < B; i++) N += (double)g_num_pos[i];
            float Nf = (float)N;
            out[0] = (float)g_loss_l / Nf + (float)g_loss_c / Nf;
            g_loss_l = 0.0; g_loss_c = 0.0; g_done = 0;
            for (int i = 0; i < B; i++) g_num_pos[i] = 0;
        }
    }
}

// ---------------- launch -----------------------------------------------------------
extern "C" void kernel_launch(void* const* d_in, const int* in_sizes, int n_in,
                              void* d_out, int out_size)
{
    const float* loc    = (const float*)d_in[0];
    const float* conf   = (const float*)d_in[1];
    const float* priors = (const float*)d_in[2];
    const float* boxes  = (const float*)d_in[3];
    const int*   labels = (const int*)  d_in[4];

    int P = in_sizes[2] / 4;
    int B = in_sizes[0] / (P * 4);
    int C = (int)((long long)in_sizes[1] / ((long long)B * P));
    int O = in_sizes[4] / B;

    dim3 g1((P + 255) / 256, B);
    k_match<<<g1, 256>>>(priors, boxes, B, P, O);

    dim3 ga((P + ACHUNK - 1) / ACHUNK, B);
    k_argmax<<<ga, 1024>>>(priors, boxes, B, P, O);

    dim3 g2((P + LTILE - 1) / LTILE, B);
    size_t smem = (size_t)LTILE * C * sizeof(float);
    k_loss<<<g2, LTHREADS, smem>>>(loc, conf, priors, boxes, labels, B, P, O, C);

    k_mine0<<<B, 1024>>>(B, P);

    int n4 = P >> 2;
    dim3 gm1((n4 + M1CHUNK - 1) / M1CHUNK, B);
    k_mine1<<<gm1, 1024>>>(B, P);

    k_mine2<<<B, 256>>>((float*)d_out, B, P, O);
}